// round 13
// baseline (speedup 1.0000x reference)
#include <cuda_runtime.h>
#include <math.h>

#define H 64
#define W 64
#define C 256
#define P 7
#define NUM_ROIS 256
#define FC (W * C)   // floats per x-row (16384)

__device__ __forceinline__ float4 fmax4(float4 a, float4 b) {
    a.x = fmaxf(a.x, b.x);
    a.y = fmaxf(a.y, b.y);
    a.z = fmaxf(a.z, b.z);
    a.w = fmaxf(a.w, b.w);
    return a;
}

// One block per (roi, i, j) bin; 64 threads = 64 float4 channel groups.
// Constant-trip-count tap grids (all loads of a batch issue back-to-back):
//   2x2 grid  (xlen,ylen <= 2):  4 taps, 1 batch
//   4x4 grid  (xlen,ylen <= 4): 16 taps as 2 batches of 8 (reg pressure)
//   fallback: 5-tap clamped rows x dynamic xlen
// Clamped taps duplicate the last valid row/col: same address -> L1 hit,
// max-unchanged. __launch_bounds__(64, 24) caps regs (~42) for 48 warps/SM.
__global__ __launch_bounds__(64, 24) void roi_pool_kernel(
    const float* __restrict__ feat,   // (H, W, C)
    const float* __restrict__ rois,   // (NUM_ROIS, 4) = x1,y1,x2,y2
    float* __restrict__ out)          // (NUM_ROIS, P, P, C)
{
    const int b  = blockIdx.x;        // r*49 + i*7 + j
    const int r  = b / (P * P);
    const int ij = b - r * (P * P);
    const int i  = ij / P;
    const int j  = ij - i * P;

    const int c4 = (int)threadIdx.x << 2;   // channel quad

    const float x1 = __ldg(&rois[r * 4 + 0]);
    const float y1 = __ldg(&rois[r * 4 + 1]);
    const float x2 = __ldg(&rois[r * 4 + 2]);
    const float y2 = __ldg(&rois[r * 4 + 3]);

    // exact reference bin math; in-range for 0<=x1<x2<=1
    const int lox   = (int)floorf(x1 * (float)H);
    const int hix   = (int)ceilf(x2 * (float)H);
    const int spanx = max(hix - lox, 1);
    const int xs    = lox + (i * spanx) / P;
    const int xe    = lox + ((i + 1) * spanx + (P - 1)) / P;
    const int xlen  = max(xe - xs, 1);

    const int loy   = (int)floorf(y1 * (float)W);
    const int hiy   = (int)ceilf(y2 * (float)W);
    const int spany = max(hiy - loy, 1);
    const int ys    = loy + (j * spany) / P;
    const int ye    = loy + ((j + 1) * spany + (P - 1)) / P;
    const int ylen  = max(ye - ys, 1);

    const float NEG = -INFINITY;
    float4 acc = make_float4(NEG, NEG, NEG, NEG);

    const float* base = feat + (size_t)xs * FC + (size_t)ys * C + c4;

    const int xm = xlen - 1;
    const int ym = ylen - 1;

    if (xlen <= 4 && ylen <= 4) {
        const int co1 = min(1, ym) * C;
        const float* r0 = base;
        const float* r1 = base + (size_t)min(1, xm) * FC;

        if (xlen <= 2 && ylen <= 2) {
            // 2x2: 4 taps, one issue batch
            const float4 v00 = *reinterpret_cast<const float4*>(r0);
            const float4 v01 = *reinterpret_cast<const float4*>(r0 + co1);
            const float4 v10 = *reinterpret_cast<const float4*>(r1);
            const float4 v11 = *reinterpret_cast<const float4*>(r1 + co1);
            acc = fmax4(fmax4(v00, v01), fmax4(v10, v11));
        } else {
            // 4x4 as two 8-load batches (rows 0-1, then rows 2-3)
            const int co2 = min(2, ym) * C;
            const int co3 = min(3, ym) * C;
            {
                const float4 a00 = *reinterpret_cast<const float4*>(r0);
                const float4 a01 = *reinterpret_cast<const float4*>(r0 + co1);
                const float4 a02 = *reinterpret_cast<const float4*>(r0 + co2);
                const float4 a03 = *reinterpret_cast<const float4*>(r0 + co3);
                const float4 a10 = *reinterpret_cast<const float4*>(r1);
                const float4 a11 = *reinterpret_cast<const float4*>(r1 + co1);
                const float4 a12 = *reinterpret_cast<const float4*>(r1 + co2);
                const float4 a13 = *reinterpret_cast<const float4*>(r1 + co3);
                acc = fmax4(acc, fmax4(fmax4(a00, a01), fmax4(a02, a03)));
                acc = fmax4(acc, fmax4(fmax4(a10, a11), fmax4(a12, a13)));
            }
            {
                const float* r2 = base + (size_t)min(2, xm) * FC;
                const float* r3 = base + (size_t)min(3, xm) * FC;
                const float4 a20 = *reinterpret_cast<const float4*>(r2);
                const float4 a21 = *reinterpret_cast<const float4*>(r2 + co1);
                const float4 a22 = *reinterpret_cast<const float4*>(r2 + co2);
                const float4 a23 = *reinterpret_cast<const float4*>(r2 + co3);
                const float4 a30 = *reinterpret_cast<const float4*>(r3);
                const float4 a31 = *reinterpret_cast<const float4*>(r3 + co1);
                const float4 a32 = *reinterpret_cast<const float4*>(r3 + co2);
                const float4 a33 = *reinterpret_cast<const float4*>(r3 + co3);
                acc = fmax4(acc, fmax4(fmax4(a20, a21), fmax4(a22, a23)));
                acc = fmax4(acc, fmax4(fmax4(a30, a31), fmax4(a32, a33)));
            }
        }
    } else {
        // fallback: 5 clamped taps per x-row, dynamic xlen
        const int co1 = min(1, ym) * C;
        const int co2 = min(2, ym) * C;
        const int co3 = min(3, ym) * C;
        const int co4 = min(4, ym) * C;
        const float* rp = base;
        for (int sx = 0; sx < xlen; ++sx) {
            const float4 v0 = *reinterpret_cast<const float4*>(rp);
            const float4 v1 = *reinterpret_cast<const float4*>(rp + co1);
            const float4 v2 = *reinterpret_cast<const float4*>(rp + co2);
            const float4 v3 = *reinterpret_cast<const float4*>(rp + co3);
            const float4 v4 = *reinterpret_cast<const float4*>(rp + co4);
            acc = fmax4(acc, fmax4(fmax4(v0, v1), fmax4(v2, fmax4(v3, v4))));
            rp += FC;
        }
        // safety for ylen > 5 (not expected with given ROI distribution)
        for (int sy = 5; sy < ylen; ++sy) {
            const float* p = base + (size_t)sy * C;
            for (int sx = 0; sx < xlen; ++sx) {
                acc = fmax4(acc, *reinterpret_cast<const float4*>(p));
                p += FC;
            }
        }
    }

    float* op = out + ((size_t)b * C) + c4;
    *reinterpret_cast<float4*>(op) = acc;
}

extern "C" void kernel_launch(void* const* d_in, const int* in_sizes, int n_in,
                              void* d_out, int out_size) {
    const float* feat = (const float*)d_in[0];
    const float* rois = (const float*)d_in[1];
    if (n_in >= 2 && in_sizes[0] == NUM_ROIS * 4 && in_sizes[1] == H * W * C) {
        feat = (const float*)d_in[1];
        rois = (const float*)d_in[0];
    }
    float* out = (float*)d_out;

    roi_pool_kernel<<<NUM_ROIS * P * P, 64>>>(feat, rois, out);
}

// round 15
// speedup vs baseline: 1.1026x; 1.1026x over previous
#include <cuda_runtime.h>
#include <math.h>

#define H 64
#define W 64
#define C 256
#define P 7
#define NUM_ROIS 256
#define NBINS (NUM_ROIS * P * P)   // 12544
#define FC (W * C)                 // floats per x-row (16384)
#define MAIN_CTAS 444
#define MAIN_THREADS 256
#define NWARPS (MAIN_CTAS * (MAIN_THREADS / 32))   // 3552

// Per-bin descriptor: {base float offset (xs*FC + ys*C), (xlen<<8)|ylen}
__device__ int2 g_desc[NBINS];

__device__ __forceinline__ float4 fmax4(float4 a, float4 b) {
    a.x = fmaxf(a.x, b.x);
    a.y = fmaxf(a.y, b.y);
    a.z = fmaxf(a.z, b.z);
    a.w = fmaxf(a.w, b.w);
    return a;
}

// Setup: exact reference bin math -> packed descriptors.
__global__ __launch_bounds__(256) void bins_kernel(const float* __restrict__ rois) {
    const int b = blockIdx.x * 256 + (int)threadIdx.x;
    if (b >= NBINS) return;
    const int r  = b / (P * P);
    const int ij = b - r * (P * P);
    const int i  = ij / P;
    const int j  = ij - i * P;

    const float x1 = __ldg(&rois[r * 4 + 0]);
    const float y1 = __ldg(&rois[r * 4 + 1]);
    const float x2 = __ldg(&rois[r * 4 + 2]);
    const float y2 = __ldg(&rois[r * 4 + 3]);

    const int lox   = (int)floorf(x1 * (float)H);
    const int hix   = (int)ceilf(x2 * (float)H);
    const int spanx = max(hix - lox, 1);
    int xs          = lox + (i * spanx) / P;
    const int xe    = lox + ((i + 1) * spanx + (P - 1)) / P;
    const int xlen  = max(xe - xs, 1);
    xs = min(max(xs, 0), H - 1);

    const int loy   = (int)floorf(y1 * (float)W);
    const int hiy   = (int)ceilf(y2 * (float)W);
    const int spany = max(hiy - loy, 1);
    int ys          = loy + (j * spany) / P;
    const int ye    = loy + ((j + 1) * spany + (P - 1)) / P;
    const int ylen  = max(ye - ys, 1);
    ys = min(max(ys, 0), W - 1);

    g_desc[b] = make_int2(xs * FC + ys * C, (xlen << 8) | ylen);
}

// Main: persistent warps. warp = bin; lane = channel quads c4 and c4+128.
// Next bin's descriptor is prefetched before processing the current bin.
// Tap grids (batched loads; clamp-dups are same-address L1 hits, max-safe):
//   2x2 -> one 8-load batch; 4x4 -> four 8-load row batches;
//   fallback -> dynamic rows x 6 clamped col taps (len <= 6 guaranteed by
//   ROI width <= 0.5 -> span <= 34; safety loop beyond just in case).
__global__ __launch_bounds__(MAIN_THREADS, 3) void roi_pool_kernel(
    const float* __restrict__ feat,   // (H, W, C)
    float* __restrict__ out)          // (NBINS, C)
{
    const int wid  = (int)threadIdx.x >> 5;
    const int lane = (int)threadIdx.x & 31;
    const int c4   = lane << 2;
    const int gw   = blockIdx.x * (MAIN_THREADS / 32) + wid;

    const float NEG = -INFINITY;

    int idx = gw;
    if (idx >= NBINS) return;
    int2 d = g_desc[idx];

    while (true) {
        const int nidx = idx + NWARPS;
        int2 dn;
        if (nidx < NBINS) dn = g_desc[nidx];   // prefetch next descriptor

        const int  base = d.x;
        const int  xlen = d.y >> 8;
        const int  ylen = d.y & 255;
        const int  xm   = xlen - 1;
        const int  ym   = ylen - 1;
        const int  co1  = min(1, ym) * C;

        const float* pb = feat + base + c4;

        float4 aL = make_float4(NEG, NEG, NEG, NEG);
        float4 aH = aL;

        if (xlen <= 2 && ylen <= 2) {
            // 8 loads, one batch
            const float* r0 = pb;
            const float* r1 = pb + (size_t)min(1, xm) * FC;
            const float4 v0 = *reinterpret_cast<const float4*>(r0);
            const float4 v1 = *reinterpret_cast<const float4*>(r0 + co1);
            const float4 v2 = *reinterpret_cast<const float4*>(r1);
            const float4 v3 = *reinterpret_cast<const float4*>(r1 + co1);
            const float4 h0 = *reinterpret_cast<const float4*>(r0 + 128);
            const float4 h1 = *reinterpret_cast<const float4*>(r0 + co1 + 128);
            const float4 h2 = *reinterpret_cast<const float4*>(r1 + 128);
            const float4 h3 = *reinterpret_cast<const float4*>(r1 + co1 + 128);
            aL = fmax4(fmax4(v0, v1), fmax4(v2, v3));
            aH = fmax4(fmax4(h0, h1), fmax4(h2, h3));
        } else if (xlen <= 4 && ylen <= 4) {
            const int co2 = min(2, ym) * C;
            const int co3 = min(3, ym) * C;
            const int ro1 = min(1, xm) * FC;
            const int ro2 = min(2, xm) * FC;
            const int ro3 = min(3, xm) * FC;
#pragma unroll
            for (int rr = 0; rr < 4; ++rr) {
                const int ro = (rr == 0) ? 0 : (rr == 1) ? ro1 : (rr == 2) ? ro2 : ro3;
                const float* rp = pb + ro;
                const float4 v0 = *reinterpret_cast<const float4*>(rp);
                const float4 v1 = *reinterpret_cast<const float4*>(rp + co1);
                const float4 v2 = *reinterpret_cast<const float4*>(rp + co2);
                const float4 v3 = *reinterpret_cast<const float4*>(rp + co3);
                const float4 h0 = *reinterpret_cast<const float4*>(rp + 128);
                const float4 h1 = *reinterpret_cast<const float4*>(rp + co1 + 128);
                const float4 h2 = *reinterpret_cast<const float4*>(rp + co2 + 128);
                const float4 h3 = *reinterpret_cast<const float4*>(rp + co3 + 128);
                aL = fmax4(aL, fmax4(fmax4(v0, v1), fmax4(v2, v3)));
                aH = fmax4(aH, fmax4(fmax4(h0, h1), fmax4(h2, h3)));
            }
        } else {
            const int co2 = min(2, ym) * C;
            const int co3 = min(3, ym) * C;
            const int co4 = min(4, ym) * C;
            const int co5 = min(5, ym) * C;
            const float* rp = pb;
            for (int sx = 0; sx < xlen; ++sx) {
                const float4 v0 = *reinterpret_cast<const float4*>(rp);
                const float4 v1 = *reinterpret_cast<const float4*>(rp + co1);
                const float4 v2 = *reinterpret_cast<const float4*>(rp + co2);
                const float4 v3 = *reinterpret_cast<const float4*>(rp + co3);
                const float4 v4 = *reinterpret_cast<const float4*>(rp + co4);
                const float4 v5 = *reinterpret_cast<const float4*>(rp + co5);
                const float4 h0 = *reinterpret_cast<const float4*>(rp + 128);
                const float4 h1 = *reinterpret_cast<const float4*>(rp + co1 + 128);
                const float4 h2 = *reinterpret_cast<const float4*>(rp + co2 + 128);
                const float4 h3 = *reinterpret_cast<const float4*>(rp + co3 + 128);
                const float4 h4 = *reinterpret_cast<const float4*>(rp + co4 + 128);
                const float4 h5 = *reinterpret_cast<const float4*>(rp + co5 + 128);
                aL = fmax4(aL, fmax4(fmax4(v0, v1), fmax4(v2, fmax4(v3, fmax4(v4, v5)))));
                aH = fmax4(aH, fmax4(fmax4(h0, h1), fmax4(h2, fmax4(h3, fmax4(h4, h5)))));
                rp += FC;
            }
            // safety for ylen > 6 (unreachable for given ROI distribution)
            for (int sy = 6; sy < ylen; ++sy) {
                const float* p = pb + sy * C;
                for (int sx = 0; sx < xlen; ++sx) {
                    aL = fmax4(aL, *reinterpret_cast<const float4*>(p));
                    aH = fmax4(aH, *reinterpret_cast<const float4*>(p + 128));
                    p += FC;
                }
            }
        }

        float* op = out + (size_t)idx * C + c4;
        *reinterpret_cast<float4*>(op)       = aL;
        *reinterpret_cast<float4*>(op + 128) = aH;

        if (nidx >= NBINS) break;
        idx = nidx;
        d   = dn;
    }
}

extern "C" void kernel_launch(void* const* d_in, const int* in_sizes, int n_in,
                              void* d_out, int out_size) {
    const float* feat = (const float*)d_in[0];
    const float* rois = (const float*)d_in[1];
    if (n_in >= 2 && in_sizes[0] == NUM_ROIS * 4 && in_sizes[1] == H * W * C) {
        feat = (const float*)d_in[1];
        rois = (const float*)d_in[0];
    }
    float* out = (float*)d_out;

    bins_kernel<<<(NBINS + 255) / 256, 256>>>(rois);
    roi_pool_kernel<<<MAIN_CTAS, MAIN_THREADS>>>(feat, out);
}